// round 7
// baseline (speedup 1.0000x reference)
#include <cuda_runtime.h>
#include <cuda_bf16.h>
#include <mma.h>
#include <math.h>
using namespace nvcuda;

#define BSZ 2
#define NSEQ 2048
#define HN 8
#define HD 32
#define EMB 256
#define PDIM 12
#define DIMT 44
#define NRAW 1056
#define CTXW 352
#define NBH 16

typedef unsigned long long u64;
typedef unsigned int u32;

// ---- packed fp32x2 (GEMMs) ----
__device__ __forceinline__ u64 pk2(float lo, float hi) {
    u64 r; asm("mov.b64 %0, {%1, %2};" : "=l"(r) : "f"(lo), "f"(hi)); return r;
}
__device__ __forceinline__ u64 bc2(float x) { return pk2(x, x); }
__device__ __forceinline__ void fma2(u64& d, u64 a, u64 b) {
    asm("fma.rn.f32x2 %0, %1, %2, %0;" : "+l"(d) : "l"(a), "l"(b));
}
__device__ __forceinline__ void upk2(u64 v, float& lo, float& hi) {
    asm("mov.b64 {%0, %1}, %2;" : "=f"(lo), "=f"(hi) : "l"(v));
}

// Scratch (allocation-free rule)
__device__ float g_praw[BSZ * NSEQ * NRAW];
__device__ float g_kb[NBH * NSEQ];
__device__ float g_ctx[BSZ * NSEQ * CTXW];
__device__ __nv_bfloat16 g_qh[NBH * NSEQ * 64];
__device__ __nv_bfloat16 g_ql[NBH * NSEQ * 64];
__device__ __nv_bfloat16 g_kh[NBH * NSEQ * 64];
__device__ __nv_bfloat16 g_kl[NBH * NSEQ * 64];
__device__ __nv_bfloat16 g_vh[NBH * NSEQ * 64];
__device__ __nv_bfloat16 g_vl[NBH * NSEQ * 64];

// ---------------- GEMM (FFMA2) ----------------
__device__ __forceinline__
void gemm_body(const float* __restrict__ A, const float* __restrict__ W,
               const float* __restrict__ bias, float* __restrict__ C,
               int K, int Nw, int ldc, int coff, int m0, int n0) {
    __shared__ float As[16][68];
    __shared__ float Bs[16][68];
    const int t = threadIdx.x;
    const int arow = t >> 2, akg = (t & 3) * 4, bk = t >> 4, bn = (t & 15) * 4;
    const int cx = (t & 15) * 4, ry = (t >> 4) * 4;
    u64 acc2[4][2];
#pragma unroll
    for (int i = 0; i < 4; i++) { acc2[i][0] = 0ull; acc2[i][1] = 0ull; }
    for (int k0 = 0; k0 < K; k0 += 16) {
        float4 a4 = *(const float4*)(A + (size_t)(m0 + arow) * K + k0 + akg);
        As[akg + 0][arow] = a4.x; As[akg + 1][arow] = a4.y;
        As[akg + 2][arow] = a4.z; As[akg + 3][arow] = a4.w;
        const float* wr = W + (size_t)(k0 + bk) * Nw;
        int gcol = n0 + bn;
        if (gcol + 3 < Nw) {
            float4 b4 = *(const float4*)(wr + gcol);
            Bs[bk][bn] = b4.x; Bs[bk][bn + 1] = b4.y; Bs[bk][bn + 2] = b4.z; Bs[bk][bn + 3] = b4.w;
        } else {
#pragma unroll
            for (int i = 0; i < 4; i++) Bs[bk][bn + i] = (gcol + i < Nw) ? wr[gcol + i] : 0.f;
        }
        __syncthreads();
#pragma unroll
        for (int kk = 0; kk < 16; kk++) {
            float4 av = *(const float4*)&As[kk][ry];
            ulonglong2 bv = *(const ulonglong2*)&Bs[kk][cx];
            u64 a0 = bc2(av.x), a1 = bc2(av.y), a2 = bc2(av.z), a3 = bc2(av.w);
            fma2(acc2[0][0], a0, bv.x); fma2(acc2[0][1], a0, bv.y);
            fma2(acc2[1][0], a1, bv.x); fma2(acc2[1][1], a1, bv.y);
            fma2(acc2[2][0], a2, bv.x); fma2(acc2[2][1], a2, bv.y);
            fma2(acc2[3][0], a3, bv.x); fma2(acc2[3][1], a3, bv.y);
        }
        __syncthreads();
    }
#pragma unroll
    for (int i = 0; i < 4; i++) {
        float c0, c1, c2, c3;
        upk2(acc2[i][0], c0, c1); upk2(acc2[i][1], c2, c3);
        float cc[4] = {c0, c1, c2, c3};
        float* crow = C + (size_t)(m0 + ry + i) * ldc + coff;
#pragma unroll
        for (int j = 0; j < 4; j++) { int col = n0 + cx + j; if (col < Nw) crow[col] = cc[j] + bias[col]; }
    }
}

struct ProjArgs { const float* W[6]; const float* bias[6]; };

__global__ __launch_bounds__(256)
void proj_kernel(const float* __restrict__ A, ProjArgs pa, float* __restrict__ C) {
    const int bx = blockIdx.x;
    int g, n0;
    if (bx < 12) { g = bx >> 2; n0 = (bx & 3) * 64; }
    else { g = 3 + ((bx - 12) >> 1); n0 = ((bx - 12) & 1) * 64; }
    const int nw = (g < 3) ? 256 : 96;
    const int coff = (g < 3) ? g * 256 : 768 + (g - 3) * 96;
    gemm_body(A, pa.W[g], pa.bias[g], C, EMB, nw, NRAW, coff, blockIdx.y * 64, n0);
}

__global__ __launch_bounds__(256)
void gemm_kernel(const float* __restrict__ A, const float* __restrict__ W,
                 const float* __restrict__ bias, float* __restrict__ C, int K, int Nw, int ldc) {
    gemm_body(A, W, bias, C, K, Nw, ldc, 0, blockIdx.y * 64, blockIdx.x * 64);
}

// ---------------- Transform: bf16 hi/lo split ----------------
__device__ __forceinline__ float softplusf(float x) { return (x > 20.f) ? x : log1pf(expf(x)); }

__global__ __launch_bounds__(128)
void transform_kernel(const float* __restrict__ coords, const float* __restrict__ w_c,
                      const float* __restrict__ w_l) {
    __shared__ float row[NRAW];
    __shared__ float c3[3];
    __shared__ float wl[HN], wc[HN];
    const int blk = blockIdx.x, b = blk >> 11, pos = blk & (NSEQ - 1);
    const int t = threadIdx.x;
    for (int i = t; i < NRAW; i += 128) row[i] = g_praw[(size_t)blk * NRAW + i];
    if (t < 3) c3[t] = coords[(size_t)blk * 3 + t];
    if (t < HN) { wl[t] = softplusf(w_l[t]); wc[t] = softplusf(w_c[t]); }
    __syncthreads();

    if (t < HN) {
        float s = 0.f;
#pragma unroll
        for (int e = 0; e < PDIM; e++) {
            float v = row[864 + t * PDIM + e] + c3[e % 3];
            s = fmaf(v, v, s);
        }
        g_kb[((size_t)(b * HN + t)) * NSEQ + pos] = -0.5f * wc[t] * s;
    }

    const float RS32 = 0.17677669529663688f;
    for (int idx = t; idx < HN * 48; idx += 128) {
        int h = idx / 48, d = idx % 48;
        float qv = 0.f, kv = 0.f, vv = 0.f;
        if (d < HD) {
            qv = row[h * HD + d] * (wl[h] * RS32);
            kv = row[256 + h * HD + d];
            vv = row[512 + h * HD + d];
        } else if (d < DIMT) {
            int e = d - HD;
            float cc = c3[e % 3];
            qv = (row[768 + h * PDIM + e] + cc) * wc[h];
            kv = row[864 + h * PDIM + e] + cc;
            vv = row[960 + h * PDIM + e] + cc;
        }
        size_t o = ((size_t)(b * HN + h) * NSEQ + pos) * 64 + d;
        __nv_bfloat16 qh = __float2bfloat16(qv);
        __nv_bfloat16 kh = __float2bfloat16(kv);
        __nv_bfloat16 vh = __float2bfloat16(vv);
        g_qh[o] = qh; g_ql[o] = __float2bfloat16(qv - __bfloat162float(qh));
        g_kh[o] = kh; g_kl[o] = __float2bfloat16(kv - __bfloat162float(kh));
        g_vh[o] = vh; g_vl[o] = __float2bfloat16(vv - __bfloat162float(vh));
    }
}

// ---------------- wmma (HMMA) flash attention v2 ----------------
// smem layout (bytes):
//   SB_S  [0, 34816)     : S f32 128x68 (ld 68); Q staging aliased at start
//   SB_KH 34816 (6144), SB_KL 40960, SB_VH 47104, SB_VL 53248  (single buffer)
//   SB_PH 59392 (20480), SB_PL 79872 (20480)   : P bf16 128x80 (ld 80)
#define SB_S  0
#define SB_KH 34816
#define SB_PH 59392
#define SB_PL 79872
#define SB_TOT 100352

__global__ __launch_bounds__(256, 2)
void attn_kernel(const unsigned char* __restrict__ mask, float* __restrict__ ctx) {
    extern __shared__ char smem[];
    float* Ss = (float*)(smem + SB_S);
    __nv_bfloat16* Kh = (__nv_bfloat16*)(smem + SB_KH);            // +0
    __nv_bfloat16* Vh = (__nv_bfloat16*)(smem + SB_KH + 12288);    // arr 2
    __nv_bfloat16* Ph = (__nv_bfloat16*)(smem + SB_PH);
    __nv_bfloat16* Pl = (__nv_bfloat16*)(smem + SB_PL);

    const int t = threadIdx.x;
    const int w = t >> 5;
    const int rb = w * 16;
    const int myrow = t >> 1, half = t & 1;
    const int i0 = blockIdx.x * 128, h = blockIdx.y, b = blockIdx.z;
    const int bh = b * HN + h;
    const float* kbg = g_kb + (size_t)bh * NSEQ;

    // ---- Q staging into SB_S (aliased; Q only read once into fragments) ----
    {
        int arr = t >> 7, r = t & 127;
        const uint4* src = (const uint4*)((arr ? g_ql : g_qh) + ((size_t)bh * NSEQ + i0 + r) * 64);
        char* dst = smem + SB_S + arr * 12288 + r * 96;
#pragma unroll
        for (int g = 0; g < 6; g++) *(uint4*)(dst + g * 16) = src[g];
    }
    __syncthreads();

    wmma::fragment<wmma::matrix_a, 16, 16, 16, __nv_bfloat16, wmma::row_major> aQh[3], aQl[3];
#pragma unroll
    for (int ks = 0; ks < 3; ks++) {
        wmma::load_matrix_sync(aQh[ks], (__nv_bfloat16*)(smem + SB_S) + rb * 48 + ks * 16, 48);
        wmma::load_matrix_sync(aQl[ks], (__nv_bfloat16*)(smem + SB_S + 12288) + rb * 48 + ks * 16, 48);
    }

    wmma::fragment<wmma::accumulator, 16, 16, 16, float> oacc[3];
#pragma unroll
    for (int ct = 0; ct < 3; ct++) wmma::fill_fragment(oacc[ct], 0.f);

    // KV prefetch mapping: thread t -> array (t>>6), row (t&63), 6 uint4 (96B)
    const int pfa = t >> 6, pfr = t & 63;
    const __nv_bfloat16* pfsrc = (pfa == 0) ? g_kh : (pfa == 1) ? g_kl
                               : (pfa == 2) ? g_vh : g_vl;
    char* pfdst = smem + SB_KH + pfa * 6144 + pfr * 96;
    uint4 pf[6];
    {
        const uint4* s = (const uint4*)(pfsrc + ((size_t)bh * NSEQ + pfr) * 64);
#pragma unroll
        for (int g = 0; g < 6; g++) pf[g] = s[g];
    }

    float lreg = 0.f, m0 = 0.f;

    for (int tt = 0; tt < 32; tt++) {
        const int j0 = tt * 64;
        __syncthreads();                       // prev tile's PV readers done with KV
#pragma unroll
        for (int g = 0; g < 6; g++) *(uint4*)(pfdst + g * 16) = pf[g];
        if (tt + 1 < 32) {                     // prefetch next (latency hidden)
            const uint4* s = (const uint4*)(pfsrc + ((size_t)bh * NSEQ + j0 + 64 + pfr) * 64);
#pragma unroll
            for (int g = 0; g < 6; g++) pf[g] = s[g];
        }
        __syncthreads();                       // KV(tt) visible

        // ---- S = Q K^T (3 splits) ----
#pragma unroll
        for (int jt = 0; jt < 4; jt++) {
            wmma::fragment<wmma::accumulator, 16, 16, 16, float> sacc;
            wmma::fill_fragment(sacc, 0.f);
#pragma unroll
            for (int ks = 0; ks < 3; ks++) {
                wmma::fragment<wmma::matrix_b, 16, 16, 16, __nv_bfloat16, wmma::col_major> bKh, bKl;
                wmma::load_matrix_sync(bKh, Kh + (jt * 16) * 48 + ks * 16, 48);
                wmma::load_matrix_sync(bKl, Kh + 3072 + (jt * 16) * 48 + ks * 16, 48);  // KL = KH + 6144B
                wmma::mma_sync(sacc, aQh[ks], bKh, sacc);
                wmma::mma_sync(sacc, aQh[ks], bKl, sacc);
                wmma::mma_sync(sacc, aQl[ks], bKh, sacc);
            }
            wmma::store_matrix_sync(Ss + rb * 68 + jt * 16, sacc, 68, wmma::mem_row_major);
        }
        __syncwarp();                          // S rows are warp-local

        // ---- scalar: bias + mask + exp, chunked (8 cols at a time) ----
        const float* srow = Ss + myrow * 68;
        const unsigned char* mrowp = mask + ((size_t)b * NSEQ + i0 + myrow) * NSEQ + j0;
        char* prh = smem + SB_PH + myrow * 160;
        char* prl = smem + SB_PL + myrow * 160;

        if (tt == 0) {
            float pm = -INFINITY;
#pragma unroll
            for (int ch = 0; ch < 4; ch++) {
                int c8 = half * 32 + ch * 8;
                float4 sa = *(const float4*)(srow + c8);
                float4 sb = *(const float4*)(srow + c8 + 4);
                float4 ka = *(const float4*)(kbg + j0 + c8);
                float4 kb4 = *(const float4*)(kbg + j0 + c8 + 4);
                float v[8] = {sa.x + ka.x, sa.y + ka.y, sa.z + ka.z, sa.w + ka.w,
                              sb.x + kb4.x, sb.y + kb4.y, sb.z + kb4.z, sb.w + kb4.w};
                u64 mk = *(const u64*)(mrowp + c8);
#pragma unroll
                for (int c = 0; c < 8; c++) {
                    if ((mk >> (8 * c)) & 0xFFull) v[c] = -INFINITY;
                    pm = fmaxf(pm, v[c]);
                }
            }
            pm = fmaxf(pm, __shfl_xor_sync(0xffffffffu, pm, 1));
            m0 = fmaxf(pm, -1e4f) + 2.f;
        }
#pragma unroll
        for (int ch = 0; ch < 4; ch++) {
            int c8 = half * 32 + ch * 8;
            float4 sa = *(const float4*)(srow + c8);
            float4 sb = *(const float4*)(srow + c8 + 4);
            float4 ka = *(const float4*)(kbg + j0 + c8);
            float4 kb4 = *(const float4*)(kbg + j0 + c8 + 4);
            float v[8] = {sa.x + ka.x, sa.y + ka.y, sa.z + ka.z, sa.w + ka.w,
                          sb.x + kb4.x, sb.y + kb4.y, sb.z + kb4.z, sb.w + kb4.w};
            u64 mk = *(const u64*)(mrowp + c8);
#pragma unroll
            for (int c = 0; c < 8; c++)
                if ((mk >> (8 * c)) & 0xFFull) v[c] = -INFINITY;
            float p[8];
#pragma unroll
            for (int c = 0; c < 8; c++) { p[c] = __expf(v[c] - m0); lreg += p[c]; }
            u32 phv[4], plv[4];
#pragma unroll
            for (int k = 0; k < 4; k++) {
                __nv_bfloat162 hh = __floats2bfloat162_rn(p[2 * k], p[2 * k + 1]);
                __nv_bfloat162 ll = __floats2bfloat162_rn(p[2 * k] - __bfloat162float(hh.x),
                                                          p[2 * k + 1] - __bfloat162float(hh.y));
                phv[k] = *(u32*)&hh;
                plv[k] = *(u32*)&ll;
            }
            *(uint4*)(prh + c8 * 2) = make_uint4(phv[0], phv[1], phv[2], phv[3]);
            *(uint4*)(prl + c8 * 2) = make_uint4(plv[0], plv[1], plv[2], plv[3]);
        }
        __syncwarp();                          // P rows are warp-local

        // ---- O += P V (3 splits) ----
#pragma unroll
        for (int kj = 0; kj < 4; kj++) {
            wmma::fragment<wmma::matrix_a, 16, 16, 16, __nv_bfloat16, wmma::row_major> pAh, pAl;
            wmma::load_matrix_sync(pAh, Ph + rb * 80 + kj * 16, 80);
            wmma::load_matrix_sync(pAl, Pl + rb * 80 + kj * 16, 80);
#pragma unroll
            for (int ct = 0; ct < 3; ct++) {
                wmma::fragment<wmma::matrix_b, 16, 16, 16, __nv_bfloat16, wmma::row_major> vBh, vBl;
                wmma::load_matrix_sync(vBh, Vh + (kj * 16) * 48 + ct * 16, 48);
                wmma::load_matrix_sync(vBl, Vh + 3072 + (kj * 16) * 48 + ct * 16, 48); // VL = VH + 6144B
                wmma::mma_sync(oacc[ct], pAh, vBh, oacc[ct]);
                wmma::mma_sync(oacc[ct], pAh, vBl, oacc[ct]);
                wmma::mma_sync(oacc[ct], pAl, vBh, oacc[ct]);
            }
        }
    }

    // ---- epilogue ----
    __syncthreads();
#pragma unroll
    for (int ct = 0; ct < 3; ct++)
        wmma::store_matrix_sync(Ss + rb * 68 + ct * 16, oacc[ct], 68, wmma::mem_row_major);
    __syncwarp();

    lreg += __shfl_xor_sync(0xffffffffu, lreg, 1);
    float inv = 1.f / lreg;
    size_t ob = ((size_t)b * NSEQ + i0 + myrow) * CTXW;
    const float* orow = Ss + myrow * 68;
    const int cbeg = half ? 24 : 0, cend = half ? 44 : 24;
    for (int c = cbeg; c < cend; c++) {
        float o = orow[c] * inv;
        if (c < HD) ctx[ob + h * HD + c] = o;
        else        ctx[ob + 256 + h * PDIM + (c - HD)] = o;
    }
}

// ---------------------------------------------------------------------------
extern "C" void kernel_launch(void* const* d_in, const int* in_sizes, int n_in,
                              void* d_out, int out_size) {
    const float* feat = (const float*)d_in[0];
    const float* coords = (const float*)d_in[1];
    const unsigned char* mask = (const unsigned char*)d_in[2];
    const float* Wo = (const float*)d_in[15];
    const float* bo = (const float*)d_in[16];
    float* out = (float*)d_out;

    void* p;
    cudaGetSymbolAddress(&p, g_praw); float* praw = (float*)p;
    cudaGetSymbolAddress(&p, g_ctx);  float* ctx = (float*)p;

    const int M = BSZ * NSEQ;
    ProjArgs pa;
    pa.W[0] = (const float*)d_in[3];  pa.bias[0] = (const float*)d_in[4];
    pa.W[1] = (const float*)d_in[5];  pa.bias[1] = (const float*)d_in[6];
    pa.W[2] = (const float*)d_in[7];  pa.bias[2] = (const float*)d_in[8];
    pa.W[3] = (const float*)d_in[9];  pa.bias[3] = (const float*)d_in[10];
    pa.W[4] = (const float*)d_in[11]; pa.bias[4] = (const float*)d_in[12];
    pa.W[5] = (const float*)d_in[13]; pa.bias[5] = (const float*)d_in[14];
    proj_kernel<<<dim3(18, M / 64), 256>>>(feat, pa, praw);

    transform_kernel<<<M, 128>>>(coords, (const float*)d_in[17], (const float*)d_in[18]);

    cudaFuncSetAttribute(attn_kernel, cudaFuncAttributeMaxDynamicSharedMemorySize, SB_TOT);
    attn_kernel<<<dim3(16, HN, BSZ), 256, SB_TOT>>>(mask, ctx);

    gemm_kernel<<<dim3(4, M / 64), 256>>>(ctx, Wo, bo, out, CTXW, 256, 256);
}

// round 8
// speedup vs baseline: 1.5259x; 1.5259x over previous
#include <cuda_runtime.h>
#include <cuda_bf16.h>
#include <math.h>

#define BSZ 2
#define NSEQ 2048
#define HN 8
#define HD 32
#define EMB 256
#define PDIM 12
#define DIMT 44
#define NRAW 1056
#define CTXW 352
#define NBH 16

typedef unsigned long long u64;
typedef unsigned int u32;

// ---- packed fp32x2 (GEMMs) ----
__device__ __forceinline__ u64 pk2(float lo, float hi) {
    u64 r; asm("mov.b64 %0, {%1, %2};" : "=l"(r) : "f"(lo), "f"(hi)); return r;
}
__device__ __forceinline__ u64 bc2(float x) { return pk2(x, x); }
__device__ __forceinline__ void fma2(u64& d, u64 a, u64 b) {
    asm("fma.rn.f32x2 %0, %1, %2, %0;" : "+l"(d) : "l"(a), "l"(b));
}
__device__ __forceinline__ void upk2(u64 v, float& lo, float& hi) {
    asm("mov.b64 {%0, %1}, %2;" : "=f"(lo), "=f"(hi) : "l"(v));
}

// ---- mma / cp.async ----
__device__ __forceinline__ u32 smem_u32(const void* p) {
    u32 a; asm("{ .reg .u64 t; cvta.to.shared.u64 t, %1; cvt.u32.u64 %0, t; }" : "=r"(a) : "l"(p));
    return a;
}
__device__ __forceinline__ void mma16816(float* c, const u32* a, u32 b0, u32 b1) {
    asm volatile("mma.sync.aligned.m16n8k16.row.col.f32.bf16.bf16.f32 "
                 "{%0,%1,%2,%3}, {%4,%5,%6,%7}, {%8,%9}, {%0,%1,%2,%3};"
                 : "+f"(c[0]), "+f"(c[1]), "+f"(c[2]), "+f"(c[3])
                 : "r"(a[0]), "r"(a[1]), "r"(a[2]), "r"(a[3]), "r"(b0), "r"(b1));
}
__device__ __forceinline__ void cp16(u32 dst, const void* src) {
    asm volatile("cp.async.cg.shared.global [%0], [%1], 16;" :: "r"(dst), "l"(src));
}
#define CP_COMMIT() asm volatile("cp.async.commit_group;" ::: "memory")
#define CP_WAIT0()  asm volatile("cp.async.wait_group 0;" ::: "memory")

__device__ __forceinline__ u32 pkb(float a, float b) {
    __nv_bfloat162 t = __floats2bfloat162_rn(a, b); return *(u32*)&t;
}

// Scratch (allocation-free rule; __device__ globals zero-initialized)
__device__ float g_praw[BSZ * NSEQ * NRAW];
__device__ float g_kb[NBH * NSEQ];
__device__ float g_ctx[BSZ * NSEQ * CTXW];
__device__ __nv_bfloat16 g_qh[NBH * NSEQ * 64];
__device__ __nv_bfloat16 g_ql[NBH * NSEQ * 64];
__device__ __nv_bfloat16 g_kh[NBH * NSEQ * 64];
__device__ __nv_bfloat16 g_kl[NBH * NSEQ * 64];
__device__ __nv_bfloat16 g_vth[NBH * 48 * NSEQ];   // V transposed [bh][d][j]
__device__ __nv_bfloat16 g_vtl[NBH * 48 * NSEQ];

// ---------------- GEMM (FFMA2) ----------------
__device__ __forceinline__
void gemm_body(const float* __restrict__ A, const float* __restrict__ W,
               const float* __restrict__ bias, float* __restrict__ C,
               int K, int Nw, int ldc, int coff, int m0, int n0) {
    __shared__ float As[16][68];
    __shared__ float Bs[16][68];
    const int t = threadIdx.x;
    const int arow = t >> 2, akg = (t & 3) * 4, bk = t >> 4, bn = (t & 15) * 4;
    const int cx = (t & 15) * 4, ry = (t >> 4) * 4;
    u64 acc2[4][2];
#pragma unroll
    for (int i = 0; i < 4; i++) { acc2[i][0] = 0ull; acc2[i][1] = 0ull; }
    for (int k0 = 0; k0 < K; k0 += 16) {
        float4 a4 = *(const float4*)(A + (size_t)(m0 + arow) * K + k0 + akg);
        As[akg + 0][arow] = a4.x; As[akg + 1][arow] = a4.y;
        As[akg + 2][arow] = a4.z; As[akg + 3][arow] = a4.w;
        const float* wr = W + (size_t)(k0 + bk) * Nw;
        int gcol = n0 + bn;
        if (gcol + 3 < Nw) {
            float4 b4 = *(const float4*)(wr + gcol);
            Bs[bk][bn] = b4.x; Bs[bk][bn + 1] = b4.y; Bs[bk][bn + 2] = b4.z; Bs[bk][bn + 3] = b4.w;
        } else {
#pragma unroll
            for (int i = 0; i < 4; i++) Bs[bk][bn + i] = (gcol + i < Nw) ? wr[gcol + i] : 0.f;
        }
        __syncthreads();
#pragma unroll
        for (int kk = 0; kk < 16; kk++) {
            float4 av = *(const float4*)&As[kk][ry];
            ulonglong2 bv = *(const ulonglong2*)&Bs[kk][cx];
            u64 a0 = bc2(av.x), a1 = bc2(av.y), a2 = bc2(av.z), a3 = bc2(av.w);
            fma2(acc2[0][0], a0, bv.x); fma2(acc2[0][1], a0, bv.y);
            fma2(acc2[1][0], a1, bv.x); fma2(acc2[1][1], a1, bv.y);
            fma2(acc2[2][0], a2, bv.x); fma2(acc2[2][1], a2, bv.y);
            fma2(acc2[3][0], a3, bv.x); fma2(acc2[3][1], a3, bv.y);
        }
        __syncthreads();
    }
#pragma unroll
    for (int i = 0; i < 4; i++) {
        float c0, c1, c2, c3;
        upk2(acc2[i][0], c0, c1); upk2(acc2[i][1], c2, c3);
        float cc[4] = {c0, c1, c2, c3};
        float* crow = C + (size_t)(m0 + ry + i) * ldc + coff;
#pragma unroll
        for (int j = 0; j < 4; j++) { int col = n0 + cx + j; if (col < Nw) crow[col] = cc[j] + bias[col]; }
    }
}

struct ProjArgs { const float* W[6]; const float* bias[6]; };

__global__ __launch_bounds__(256)
void proj_kernel(const float* __restrict__ A, ProjArgs pa, float* __restrict__ C) {
    const int bx = blockIdx.x;
    int g, n0;
    if (bx < 12) { g = bx >> 2; n0 = (bx & 3) * 64; }
    else { g = 3 + ((bx - 12) >> 1); n0 = ((bx - 12) & 1) * 64; }
    const int nw = (g < 3) ? 256 : 96;
    const int coff = (g < 3) ? g * 256 : 768 + (g - 3) * 96;
    gemm_body(A, pa.W[g], pa.bias[g], C, EMB, nw, NRAW, coff, blockIdx.y * 64, n0);
}

__global__ __launch_bounds__(256)
void gemm_kernel(const float* __restrict__ A, const float* __restrict__ W,
                 const float* __restrict__ bias, float* __restrict__ C, int K, int Nw, int ldc) {
    gemm_body(A, W, bias, C, K, Nw, ldc, 0, blockIdx.y * 64, blockIdx.x * 64);
}

// ---------------- Transform: bf16 hi/lo split; V transposed ----------------
__device__ __forceinline__ float softplusf(float x) { return (x > 20.f) ? x : log1pf(expf(x)); }

__global__ __launch_bounds__(128)
void transform_kernel(const float* __restrict__ coords, const float* __restrict__ w_c,
                      const float* __restrict__ w_l) {
    __shared__ float row[NRAW];
    __shared__ float c3[3];
    __shared__ float wl[HN], wc[HN];
    const int blk = blockIdx.x, b = blk >> 11, pos = blk & (NSEQ - 1);
    const int t = threadIdx.x;
    for (int i = t; i < NRAW; i += 128) row[i] = g_praw[(size_t)blk * NRAW + i];
    if (t < 3) c3[t] = coords[(size_t)blk * 3 + t];
    if (t < HN) { wl[t] = softplusf(w_l[t]); wc[t] = softplusf(w_c[t]); }
    __syncthreads();

    if (t < HN) {
        float s = 0.f;
#pragma unroll
        for (int e = 0; e < PDIM; e++) {
            float v = row[864 + t * PDIM + e] + c3[e % 3];
            s = fmaf(v, v, s);
        }
        g_kb[((size_t)(b * HN + t)) * NSEQ + pos] = -0.5f * wc[t] * s;
    }

    const float RS32 = 0.17677669529663688f;
    for (int idx = t; idx < HN * 48; idx += 128) {
        int h = idx / 48, d = idx % 48;
        float qv = 0.f, kv = 0.f, vv = 0.f;
        if (d < HD) {
            qv = row[h * HD + d] * (wl[h] * RS32);
            kv = row[256 + h * HD + d];
            vv = row[512 + h * HD + d];
        } else if (d < DIMT) {
            int e = d - HD;
            float cc = c3[e % 3];
            qv = (row[768 + h * PDIM + e] + cc) * wc[h];
            kv = row[864 + h * PDIM + e] + cc;
            vv = row[960 + h * PDIM + e] + cc;
        }
        int bh = b * HN + h;
        size_t o = ((size_t)bh * NSEQ + pos) * 64 + d;
        __nv_bfloat16 qh = __float2bfloat16(qv);
        __nv_bfloat16 kh = __float2bfloat16(kv);
        __nv_bfloat16 vh = __float2bfloat16(vv);
        g_qh[o] = qh; g_ql[o] = __float2bfloat16(qv - __bfloat162float(qh));
        g_kh[o] = kh; g_kl[o] = __float2bfloat16(kv - __bfloat162float(kh));
        size_t vo = ((size_t)bh * 48 + d) * NSEQ + pos;
        g_vth[vo] = vh;
        g_vtl[vo] = __float2bfloat16(vv - __bfloat162float(vh));
    }
}

// ---------------- FA2-style mma.sync flash attention ----------------
// smem: buf0 [0,28672): Kh(7168,ld56) Kl Vth(7168,ld72) Vtl ; buf1 [28672,57344); red @57344
#define BUF_SZ 28672
#define OFF_K  0
#define OFF_KL 7168
#define OFF_V  14336
#define OFF_VL 21504
#define SB_RED 57344
#define SB_TOT 58368

__global__ __launch_bounds__(256, 2)
void attn_kernel(const unsigned char* __restrict__ mask, float* __restrict__ ctx) {
    extern __shared__ char smem[];
    const u32 sb = smem_u32(smem);
    const int t = threadIdx.x;
    const int w = t >> 5, lane = t & 31;
    const int gid = lane >> 2, tig = lane & 3;
    const int rb = w * 16;
    const int i0 = blockIdx.x * 128, h = blockIdx.y, b = blockIdx.z;
    const int bh = b * HN + h;
    const float* kbg = g_kb + (size_t)bh * NSEQ;

    // ---- issue KV(0) via cp.async ----
    {
#pragma unroll
        for (int rep = 0; rep < 3; rep++) {
            int i = t + rep * 256;
            int arr = i / 384, rem = i % 384;
            int krow = rem / 6, kch = rem % 6;
            const char* ks = (const char*)(arr ? g_kl : g_kh) + (((size_t)bh * NSEQ + krow) << 7) + kch * 16;
            cp16(sb + OFF_K + arr * 7168 + krow * 112 + kch * 16, ks);
            int vrow = rem / 8, vch = rem % 8;
            const char* vs = (const char*)(arr ? g_vtl : g_vth) + (((size_t)bh * 48 + vrow) << 12) + vch * 16;
            cp16(sb + OFF_V + arr * 7168 + vrow * 144 + vch * 16, vs);
        }
        CP_COMMIT();
    }

    // ---- stage Q into buf1, then load fragments ----
    {
        int arr = t >> 7, r = t & 127;
        const uint4* src = (const uint4*)((arr ? g_ql : g_qh) + ((size_t)bh * NSEQ + i0 + r) * 64);
        char* dst = smem + BUF_SZ + arr * 12288 + r * 96;
#pragma unroll
        for (int g = 0; g < 6; g++) *(uint4*)(dst + g * 16) = src[g];
    }
    __syncthreads();

    u32 qfh[3][4], qfl[3][4];
    {
        const char* Qb = smem + BUF_SZ;
#pragma unroll
        for (int ks = 0; ks < 3; ks++) {
            int co = ks * 32 + 4 * tig;  // bytes
            int r0 = (rb + gid) * 96, r1 = (rb + gid + 8) * 96;
            qfh[ks][0] = *(const u32*)(Qb + r0 + co);
            qfh[ks][1] = *(const u32*)(Qb + r1 + co);
            qfh[ks][2] = *(const u32*)(Qb + r0 + co + 16);
            qfh[ks][3] = *(const u32*)(Qb + r1 + co + 16);
            qfl[ks][0] = *(const u32*)(Qb + 12288 + r0 + co);
            qfl[ks][1] = *(const u32*)(Qb + 12288 + r1 + co);
            qfl[ks][2] = *(const u32*)(Qb + 12288 + r0 + co + 16);
            qfl[ks][3] = *(const u32*)(Qb + 12288 + r1 + co + 16);
        }
    }

    float oc[6][4];
#pragma unroll
    for (int ct = 0; ct < 6; ct++)
#pragma unroll
        for (int i = 0; i < 4; i++) oc[ct][i] = 0.f;

    float la = 0.f, lb = 0.f, m0a = 0.f, m0b = 0.f;
    const unsigned char* mrow0 = mask + ((size_t)(b * NSEQ + i0 + rb + gid)) * NSEQ + 2 * tig;

    for (int tt = 0; tt < 32; tt++) {
        const int j0 = tt * 64;
        CP_WAIT0();
        __syncthreads();
        if (tt + 1 < 32) {
            u32 nb_base = sb + ((tt + 1) & 1) * BUF_SZ;
            int jn = j0 + 64;
#pragma unroll
            for (int rep = 0; rep < 3; rep++) {
                int i = t + rep * 256;
                int arr = i / 384, rem = i % 384;
                int krow = rem / 6, kch = rem % 6;
                const char* ks = (const char*)(arr ? g_kl : g_kh) + (((size_t)bh * NSEQ + jn + krow) << 7) + kch * 16;
                cp16(nb_base + OFF_K + arr * 7168 + krow * 112 + kch * 16, ks);
                int vrow = rem / 8, vch = rem % 8;
                const char* vs = (const char*)(arr ? g_vtl : g_vth) + (((size_t)bh * 48 + vrow) << 12) + (size_t)jn * 2 + vch * 16;
                cp16(nb_base + OFF_V + arr * 7168 + vrow * 144 + vch * 16, vs);
            }
            CP_COMMIT();
        }
        const char* Bb = smem + (tt & 1) * BUF_SZ;

        // ---- S = Q K^T, register accumulators ----
        float sc[8][4];
#pragma unroll
        for (int nb = 0; nb < 8; nb++)
#pragma unroll
            for (int i = 0; i < 4; i++) sc[nb][i] = 0.f;
#pragma unroll
        for (int nb = 0; nb < 8; nb++) {
            int rowb = (nb * 8 + gid) * 112 + 4 * tig;
#pragma unroll
            for (int ks = 0; ks < 3; ks++) {
                u32 kh0 = *(const u32*)(Bb + OFF_K + rowb + 32 * ks);
                u32 kh1 = *(const u32*)(Bb + OFF_K + rowb + 32 * ks + 16);
                u32 kl0 = *(const u32*)(Bb + OFF_KL + rowb + 32 * ks);
                u32 kl1 = *(const u32*)(Bb + OFF_KL + rowb + 32 * ks + 16);
                mma16816(sc[nb], qfh[ks], kh0, kh1);
                mma16816(sc[nb], qfh[ks], kl0, kl1);
                mma16816(sc[nb], qfl[ks], kh0, kh1);
            }
        }

        // ---- bias + mask (in fragments) ----
#pragma unroll
        for (int nb = 0; nb < 8; nb++) {
            float2 kb2 = *(const float2*)(kbg + j0 + nb * 8 + 2 * tig);
            unsigned short mk0 = *(const unsigned short*)(mrow0 + j0 + nb * 8);
            unsigned short mk1 = *(const unsigned short*)(mrow0 + 8 * NSEQ + j0 + nb * 8);
            sc[nb][0] = (mk0 & 0xFF) ? -INFINITY : sc[nb][0] + kb2.x;
            sc[nb][1] = (mk0 >> 8)  ? -INFINITY : sc[nb][1] + kb2.y;
            sc[nb][2] = (mk1 & 0xFF) ? -INFINITY : sc[nb][2] + kb2.x;
            sc[nb][3] = (mk1 >> 8)  ? -INFINITY : sc[nb][3] + kb2.y;
        }
        if (tt == 0) {
            float ma = -INFINITY, mb = -INFINITY;
#pragma unroll
            for (int nb = 0; nb < 8; nb++) {
                ma = fmaxf(ma, fmaxf(sc[nb][0], sc[nb][1]));
                mb = fmaxf(mb, fmaxf(sc[nb][2], sc[nb][3]));
            }
            ma = fmaxf(ma, __shfl_xor_sync(0xffffffffu, ma, 1));
            ma = fmaxf(ma, __shfl_xor_sync(0xffffffffu, ma, 2));
            mb = fmaxf(mb, __shfl_xor_sync(0xffffffffu, mb, 1));
            mb = fmaxf(mb, __shfl_xor_sync(0xffffffffu, mb, 2));
            m0a = fmaxf(ma, -1e4f) + 2.f;
            m0b = fmaxf(mb, -1e4f) + 2.f;
        }

        // ---- exp in-register, convert S-frags -> P A-frags, PV ----
#pragma unroll
        for (int kj = 0; kj < 4; kj++) {
            const int n0 = 2 * kj, n1 = 2 * kj + 1;
            float p0 = __expf(sc[n0][0] - m0a), p1 = __expf(sc[n0][1] - m0a);
            float p2 = __expf(sc[n0][2] - m0b), p3 = __expf(sc[n0][3] - m0b);
            float p4 = __expf(sc[n1][0] - m0a), p5 = __expf(sc[n1][1] - m0a);
            float p6 = __expf(sc[n1][2] - m0b), p7 = __expf(sc[n1][3] - m0b);
            la += (p0 + p1) + (p4 + p5);
            lb += (p2 + p3) + (p6 + p7);
            u32 pha[4], pla[4];
            pha[0] = pkb(p0, p1); pha[1] = pkb(p2, p3);
            pha[2] = pkb(p4, p5); pha[3] = pkb(p6, p7);
            {
                __nv_bfloat162 h0 = *(__nv_bfloat162*)&pha[0];
                __nv_bfloat162 h1 = *(__nv_bfloat162*)&pha[1];
                __nv_bfloat162 h2 = *(__nv_bfloat162*)&pha[2];
                __nv_bfloat162 h3 = *(__nv_bfloat162*)&pha[3];
                pla[0] = pkb(p0 - __bfloat162float(h0.x), p1 - __bfloat162float(h0.y));
                pla[1] = pkb(p2 - __bfloat162float(h1.x), p3 - __bfloat162float(h1.y));
                pla[2] = pkb(p4 - __bfloat162float(h2.x), p5 - __bfloat162float(h2.y));
                pla[3] = pkb(p6 - __bfloat162float(h3.x), p7 - __bfloat162float(h3.y));
            }
            int vo = kj * 32 + 4 * tig;
#pragma unroll
            for (int ct = 0; ct < 6; ct++) {
                int ro = (ct * 8 + gid) * 144;
                u32 vh0 = *(const u32*)(Bb + OFF_V + ro + vo);
                u32 vh1 = *(const u32*)(Bb + OFF_V + ro + vo + 16);
                u32 vl0 = *(const u32*)(Bb + OFF_VL + ro + vo);
                u32 vl1 = *(const u32*)(Bb + OFF_VL + ro + vo + 16);
                mma16816(oc[ct], pha, vh0, vh1);
                mma16816(oc[ct], pha, vl0, vl1);
                mma16816(oc[ct], pla, vh0, vh1);
            }
        }
    }

    // ---- epilogue: l reduce + O via smem, normalized write ----
    la += __shfl_xor_sync(0xffffffffu, la, 1);
    la += __shfl_xor_sync(0xffffffffu, la, 2);
    lb += __shfl_xor_sync(0xffffffffu, lb, 1);
    lb += __shfl_xor_sync(0xffffffffu, lb, 2);
    float* red = (float*)(smem + SB_RED);
    float* Es = (float*)smem;   // [128][50], aliases buf0 (last KV in buf1)
#pragma unroll
    for (int ct = 0; ct < 6; ct++) {
        *(float2*)&Es[(rb + gid) * 50 + ct * 8 + 2 * tig] = make_float2(oc[ct][0], oc[ct][1]);
        *(float2*)&Es[(rb + gid + 8) * 50 + ct * 8 + 2 * tig] = make_float2(oc[ct][2], oc[ct][3]);
    }
    if (tig == 0) { red[rb + gid] = la; red[rb + gid + 8] = lb; }
    __syncthreads();

    int row = t >> 1, half = t & 1;
    float inv = 1.f / red[row];
    size_t ob = ((size_t)b * NSEQ + i0 + row) * CTXW;
    const float* orow = Es + row * 50;
    const int cbeg = half ? 24 : 0, cend = half ? 44 : 24;
    for (int c = cbeg; c < cend; c++) {
        float o = orow[c] * inv;
        if (c < HD) ctx[ob + h * HD + c] = o;
        else        ctx[ob + 256 + h * PDIM + (c - HD)] = o;
    }
}

// ---------------------------------------------------------------------------
extern "C" void kernel_launch(void* const* d_in, const int* in_sizes, int n_in,
                              void* d_out, int out_size) {
    const float* feat = (const float*)d_in[0];
    const float* coords = (const float*)d_in[1];
    const unsigned char* mask = (const unsigned char*)d_in[2];
    const float* Wo = (const float*)d_in[15];
    const float* bo = (const float*)d_in[16];
    float* out = (float*)d_out;

    void* p;
    cudaGetSymbolAddress(&p, g_praw); float* praw = (float*)p;
    cudaGetSymbolAddress(&p, g_ctx);  float* ctx = (float*)p;

    const int M = BSZ * NSEQ;
    ProjArgs pa;
    pa.W[0] = (const float*)d_in[3];  pa.bias[0] = (const float*)d_in[4];
    pa.W[1] = (const float*)d_in[5];  pa.bias[1] = (const float*)d_in[6];
    pa.W[2] = (const float*)d_in[7];  pa.bias[2] = (const float*)d_in[8];
    pa.W[3] = (const float*)d_in[9];  pa.bias[3] = (const float*)d_in[10];
    pa.W[4] = (const float*)d_in[11]; pa.bias[4] = (const float*)d_in[12];
    pa.W[5] = (const float*)d_in[13]; pa.bias[5] = (const float*)d_in[14];
    proj_kernel<<<dim3(18, M / 64), 256>>>(feat, pa, praw);

    transform_kernel<<<M, 128>>>(coords, (const float*)d_in[17], (const float*)d_in[18]);

    cudaFuncSetAttribute(attn_kernel, cudaFuncAttributeMaxDynamicSharedMemorySize, SB_TOT);
    attn_kernel<<<dim3(16, HN, BSZ), 256, SB_TOT>>>(mask, ctx);

    gemm_kernel<<<dim3(4, M / 64), 256>>>(ctx, Wo, bo, out, CTXW, 256, 256);
}